// round 8
// baseline (speedup 1.0000x reference)
#include <cuda_runtime.h>

// SphericalExpansion: per-edge radial×angular outer product scattered into
// out[idx_i, z[idx_j], n, m]  (20000, 4, 8, 16) fp32.
//
// Phase 1 (edge_prep): per edge, compute
//   rb = (idx_i*4 + zarr[idx_j]) * 128            (atomic base offset)
//   B  = exp(4d/3),  sc = exp(-2d^2) * fc(d)       (radial factorization)
//   Y[16] real spherical harmonics, stored as 4 float4 quads
// Phase 2 (hot loop): two edges per warp. Lane p=(h, pos) runs ONE packed
// f32x2 Horner giving rows (l,nl),(l,nl+4) [l=pos>>2, nl=pos&3]:
//   acc[row] = sc * Horner_k( W[row,k]*C_k ; B ),  C_k = exp(-2 c_k^2)
// bridges via 4 uniform-register shuffles to scatter role (quads pos, pos+16),
// multiplies by the preloaded Y quad, commits 2x red.global.add.v4.f32.

#define PI_F 3.14159265358979f
#define MAX_EDGES 800000

__device__ float4 g_hdr[MAX_EDGES];        // {rb-as-bits, B, sc, 0}
__device__ float4 g_y4[MAX_EDGES * 4];     // Y quads: [e][mq]

typedef unsigned long long u64_t;

__device__ __forceinline__ u64_t pack2(float lo, float hi) {
    u64_t r; asm("mov.b64 %0, {%1, %2};" : "=l"(r) : "f"(lo), "f"(hi)); return r;
}
__device__ __forceinline__ void unpack2(u64_t v, float& lo, float& hi) {
    asm("mov.b64 {%0, %1}, %2;" : "=f"(lo), "=f"(hi) : "l"(v));
}
__device__ __forceinline__ u64_t fma2(u64_t a, u64_t b, u64_t c) {
    u64_t d; asm("fma.rn.f32x2 %0, %1, %2, %3;" : "=l"(d) : "l"(a), "l"(b), "l"(c));
    return d;
}
__device__ __forceinline__ u64_t mul2(u64_t a, u64_t b) {
    u64_t d; asm("mul.rn.f32x2 %0, %1, %2;" : "=l"(d) : "l"(a), "l"(b));
    return d;
}
__device__ __forceinline__ void red_add_v4(float* p, float a, float b, float c, float d) {
    asm volatile("red.global.add.v4.f32 [%0], {%1,%2,%3,%4};"
                 :: "l"(p), "f"(a), "f"(b), "f"(c), "f"(d) : "memory");
}

__global__ __launch_bounds__(512)
void edge_prep_kernel(const float* __restrict__ dist,
                      const float* __restrict__ dirs,
                      const int*   __restrict__ zarr,
                      const int*   __restrict__ idx_i,
                      const int*   __restrict__ idx_j,
                      int n_edges)
{
    int e = blockIdx.x * blockDim.x + threadIdx.x;
    if (e >= n_edges) return;

    const int rb = (idx_i[e] * 4 + zarr[idx_j[e]]) * 128;

    const float d  = dist[e];
    const float x  = dirs[3 * e + 0];
    const float y  = dirs[3 * e + 1];
    const float zc = dirs[3 * e + 2];

    float t  = fminf(fmaxf((d - 4.5f) * 2.0f, 0.0f), 1.0f);
    float fc = 0.5f * (__cosf(t * PI_F) + 1.0f);
    float A  = __expf(-2.0f * d * d);
    float B  = __expf((4.0f / 3.0f) * d);

    g_hdr[e] = make_float4(__int_as_float(rb), B, A * fc, 0.0f);

    const float x2 = x * x, y2 = y * y, z2 = zc * zc;
    g_y4[e * 4 + 0] = make_float4(
        0.28209479177387814f,
        0.4886025119029199f * y,
        0.4886025119029199f * zc,
        0.4886025119029199f * x);
    g_y4[e * 4 + 1] = make_float4(
        1.0925484305920792f * x * y,
        1.0925484305920792f * y * zc,
        0.31539156525252005f * (3.0f * z2 - 1.0f),
        1.0925484305920792f * x * zc);
    g_y4[e * 4 + 2] = make_float4(
        0.5462742152960396f * (x2 - y2),
        0.5900435899266435f * y * (3.0f * x2 - y2),
        2.890611442640554f  * x * y * zc,
        0.4570457994644658f * y * (5.0f * z2 - 1.0f));
    g_y4[e * 4 + 3] = make_float4(
        0.3731763325901154f * zc * (5.0f * z2 - 3.0f),
        0.4570457994644658f * x * (5.0f * z2 - 1.0f),
        1.445305721320277f  * zc * (x2 - y2),
        0.5900435899266435f * x * (x2 - 3.0f * y2));
}

__global__ __launch_bounds__(256)
void sph_expand_kernel(
    const float* __restrict__ W,      // (4, 8, 16) row-major = (32, 16)
    float*       __restrict__ out,    // (N_ATOMS, 4, 8, 16)
    int n_edges)
{
    const unsigned FULL = 0xffffffffu;
    const int lane = threadIdx.x & 31;
    const int h    = lane >> 4;        // which edge of the pair
    const int pos  = lane & 15;

    const int gw = (blockIdx.x * blockDim.x + threadIdx.x) >> 5;
    const int nw = (gridDim.x * blockDim.x) >> 5;

    // ---- compute role: rows (l, nl) and (l, nl+4), l = pos>>2, nl = pos&3 ----
    const int lrow = pos >> 2;
    const int nl   = pos & 3;
    const int ln0  = lrow * 8 + nl;
    const int ln1  = ln0 + 4;

    // Packed W rows, pre-scaled by C_k = exp(-2 c_k^2).
    u64_t wp[16];
    #pragma unroll
    for (int k = 0; k < 16; ++k) {
        float ck = (float)k * (5.0f / 15.0f);
        float C  = __expf(-2.0f * ck * ck);
        wp[k] = pack2(W[ln0 * 16 + k] * C, W[ln1 * 16 + k] * C);
    }

    // ---- scatter role: lane (h,pos) -> quads pos and pos+16 ----
    const int n0 = pos >> 2;
    const int mq = pos & 3;
    const int lA = (mq == 0) ? 0 : (mq == 3 ? 3 : 2);
    const int lB = (mq == 0) ? 1 : (mq == 1 ? 2 : 3);
    const int srcA = (lane & 16) + lA * 4 + n0;
    const int srcB = (lane & 16) + lB * 4 + n0;

    for (int e0 = 2 * gw; e0 < n_edges; e0 += 2 * nw) {
        const int  myE   = e0 + h;
        const bool valid = myE < n_edges;
        const int  le    = valid ? myE : (n_edges - 1);

        const float4 hv = g_hdr[le];               // broadcast within half
        const float4 yv = g_y4[le * 4 + mq];       // this lane's Y quad
        const int    rb = __float_as_int(hv.x);
        const float  B  = hv.y;
        const float  sc = hv.z;

        // ---- packed Horner: both rows at once ----
        const u64_t Bp  = pack2(B, B);
        u64_t acc = wp[15];
        #pragma unroll
        for (int k = 14; k >= 0; --k) acc = fma2(acc, Bp, wp[k]);
        acc = mul2(acc, pack2(sc, sc));

        float c0, c1;                 // c0: row (l,nl)   c1: row (l,nl+4)
        unpack2(acc, c0, c1);

        // ---- bridge: 4 shuffles, uniform source registers ----
        const float aA0 = __shfl_sync(FULL, c0, srcA);
        const float aB0 = __shfl_sync(FULL, c0, srcB);
        const float aA1 = __shfl_sync(FULL, c1, srcA);
        const float aB1 = __shfl_sync(FULL, c1, srcB);

        // out offset: rb + quad*4 ; quads pos and pos+16.
        const size_t base = (size_t)rb + (size_t)pos * 4;
        if (valid) {
            red_add_v4(out + base,      aA0 * yv.x, aB0 * yv.y, aB0 * yv.z, aB0 * yv.w);
            red_add_v4(out + base + 64, aA1 * yv.x, aB1 * yv.y, aB1 * yv.z, aB1 * yv.w);
        }
    }
}

extern "C" void kernel_launch(void* const* d_in, const int* in_sizes, int n_in,
                              void* d_out, int out_size) {
    const float* dist = (const float*)d_in[0];
    const float* dirs = (const float*)d_in[1];
    const float* W    = (const float*)d_in[2];
    // d_in[3] = centers: analytic linspace(0, RC, 16)
    const int* z      = (const int*)d_in[4];
    const int* idx_i  = (const int*)d_in[5];
    const int* idx_j  = (const int*)d_in[6];
    int n_edges = in_sizes[0];
    if (n_edges > MAX_EDGES) n_edges = MAX_EDGES;   // scratch capacity (spec: 800000)

    cudaMemsetAsync(d_out, 0, (size_t)out_size * sizeof(float), 0);

    edge_prep_kernel<<<(n_edges + 511) / 512, 512>>>(dist, dirs, z, idx_i, idx_j, n_edges);

    const int block = 256;
    const int grid  = 2368;    // 148 SMs x 16 blocks, grid-stride over edge pairs
    sph_expand_kernel<<<grid, block>>>(W, (float*)d_out, n_edges);
}

// round 9
// speedup vs baseline: 1.4638x; 1.4638x over previous
#include <cuda_runtime.h>

// SphericalExpansion: per-edge radial×angular outer product scattered into
// out[idx_i, z[idx_j], n, m]  (20000, 4, 8, 16) fp32.
//
// Key idea: RIln(d) = fc(d) * sum_k exp(-2(d-c_k)^2) * W[l*8+n, k] is a smooth
// 1-D function of d per row. Precompute it EXACTLY on a 2048-interval grid in
// a packed layout T[j][pos] = (RIln[ln0](d_j), RIln[ln1](d_j)) and replace all
// radial math (2 exp + cos + 16-FMA dot) in the hot loop with a linear interp:
// 2 packed ops, zero MUFU.
//
// Hot loop: two edges per warp (halves h). Lane (h,pos): ln0=(pos>>2)*8+(pos&3),
// ln1=ln0+4. Bridge to scatter role (quads pos, pos+16) via 4 uniform-register
// shuffles; Ylm computed inline per half; 2x red.global.add.v4.f32 per lane.

#define PI_F 3.14159265358979f
#define MAX_EDGES 800000
#define NKNOT 2048                    // intervals; knots = NKNOT+1
#define DSCALE ((float)NKNOT / 5.0f)  // d -> knot index
#define DSTEP  (5.0f / (float)NKNOT)

__device__ int    g_rbase[MAX_EDGES];
__device__ float2 g_tab[(NKNOT + 1) * 16];   // [knot][pos] = (row ln0, row ln1)

typedef unsigned long long u64_t;

__device__ __forceinline__ u64_t pack2(float lo, float hi) {
    u64_t r; asm("mov.b64 %0, {%1, %2};" : "=l"(r) : "f"(lo), "f"(hi)); return r;
}
__device__ __forceinline__ void unpack2(u64_t v, float& lo, float& hi) {
    asm("mov.b64 {%0, %1}, %2;" : "=f"(lo), "=f"(hi) : "l"(v));
}
__device__ __forceinline__ u64_t fma2(u64_t a, u64_t b, u64_t c) {
    u64_t d; asm("fma.rn.f32x2 %0, %1, %2, %3;" : "=l"(d) : "l"(a), "l"(b), "l"(c));
    return d;
}
__device__ __forceinline__ u64_t mul2(u64_t a, u64_t b) {
    u64_t d; asm("mul.rn.f32x2 %0, %1, %2;" : "=l"(d) : "l"(a), "l"(b));
    return d;
}
__device__ __forceinline__ void red_add_v4(float* p, float a, float b, float c, float d) {
    asm volatile("red.global.add.v4.f32 [%0], {%1,%2,%3,%4};"
                 :: "l"(p), "f"(a), "f"(b), "f"(c), "f"(d) : "memory");
}

// ---- one-time-per-launch table build: exact radial function ----
__global__ __launch_bounds__(256)
void build_table_kernel(const float* __restrict__ W)   // (32, 16)
{
    int t = blockIdx.x * blockDim.x + threadIdx.x;
    if (t >= (NKNOT + 1) * 16) return;
    int j   = t >> 4;
    int pos = t & 15;
    int ln0 = (pos >> 2) * 8 + (pos & 3);
    int ln1 = ln0 + 4;

    float d  = (float)j * DSTEP;
    float tt = fminf(fmaxf((d - 4.5f) * 2.0f, 0.0f), 1.0f);
    float fc = 0.5f * (cosf(tt * PI_F) + 1.0f);

    float a0 = 0.f, a1 = 0.f;
    #pragma unroll
    for (int k = 0; k < 16; ++k) {
        float ck = (float)k * (5.0f / 15.0f);
        float u  = d - ck;
        float g  = expf(-2.0f * u * u);
        a0 = fmaf(g, W[ln0 * 16 + k], a0);
        a1 = fmaf(g, W[ln1 * 16 + k], a1);
    }
    g_tab[t] = make_float2(a0 * fc, a1 * fc);
}

__global__ __launch_bounds__(512)
void build_rid_kernel(const int* __restrict__ idx_i,
                      const int* __restrict__ idx_j,
                      const int* __restrict__ zarr,
                      int n_edges)
{
    int e = blockIdx.x * blockDim.x + threadIdx.x;
    if (e < n_edges)
        g_rbase[e] = (idx_i[e] * 4 + zarr[idx_j[e]]) * 128;
}

__global__ __launch_bounds__(256)
void sph_expand_kernel(
    const float* __restrict__ dist,
    const float* __restrict__ dirs,
    float*       __restrict__ out,    // (N_ATOMS, 4, 8, 16)
    int n_edges)
{
    const unsigned FULL = 0xffffffffu;
    const int lane = threadIdx.x & 31;
    const int h    = lane >> 4;        // which edge of the pair
    const int pos  = lane & 15;

    const int gw = (blockIdx.x * blockDim.x + threadIdx.x) >> 5;
    const int nw = (gridDim.x * blockDim.x) >> 5;

    // scatter role: quads pos and pos+16. Quad q: n0=q>>2, mq=q&3.
    // l(m): mq0->{0,1,1,1} mq1->{2,2,2,2} mq2->{2,3,3,3} mq3->{3,3,3,3}
    const int n0 = pos >> 2;
    const int mq = pos & 3;
    const int lA = (mq == 0) ? 0 : (mq == 3 ? 3 : 2);
    const int lB = (mq == 0) ? 1 : (mq == 1 ? 2 : 3);
    const int srcA = (lane & 16) + lA * 4 + n0;   // compute-role lane of (lA, n0)
    const int srcB = (lane & 16) + lB * 4 + n0;

    for (int e0 = 2 * gw; e0 < n_edges; e0 += 2 * nw) {
        const int  myE   = e0 + h;
        const bool valid = myE < n_edges;
        const int  le    = valid ? myE : (n_edges - 1);

        const int   rb = g_rbase[le];       // broadcast per half
        const float d  = dist[le];
        const float x  = dirs[3 * le + 0];
        const float y  = dirs[3 * le + 1];
        const float zc = dirs[3 * le + 2];

        // ---- radial via table lerp (this lane's two rows, both halves' d) ----
        float u = d * DSCALE;
        int   j = __float2int_rd(u);
        j = min(max(j, 0), NKNOT - 1);
        float f = u - (float)j;

        const float2 t0 = g_tab[j * 16 + pos];
        const float2 t1 = g_tab[(j + 1) * 16 + pos];
        // acc = t0*(1-f) + t1*f
        const u64_t fp  = pack2(f, f);
        const u64_t gp  = pack2(1.0f - f, 1.0f - f);
        u64_t acc = fma2(pack2(t1.x, t1.y), fp,
                         mul2(pack2(t0.x, t0.y), gp));

        float c0, c1;                 // c0: row ln0   c1: row ln1
        unpack2(acc, c0, c1);

        // ---- bridge: 4 shuffles, uniform source registers ----
        const float aA0 = __shfl_sync(FULL, c0, srcA);
        const float aB0 = __shfl_sync(FULL, c0, srcB);
        const float aA1 = __shfl_sync(FULL, c1, srcA);
        const float aB1 = __shfl_sync(FULL, c1, srcB);

        // ---- real spherical harmonics l<=3 (this half's direction) ----
        const float x2 = x * x, y2 = y * y, z2 = zc * zc;
        const float Y0  = 0.28209479177387814f;
        const float Y1  = 0.4886025119029199f * y;
        const float Y2  = 0.4886025119029199f * zc;
        const float Y3  = 0.4886025119029199f * x;
        const float Y4  = 1.0925484305920792f * x * y;
        const float Y5  = 1.0925484305920792f * y * zc;
        const float Y6  = 0.31539156525252005f * (3.0f * z2 - 1.0f);
        const float Y7  = 1.0925484305920792f * x * zc;
        const float Y8  = 0.5462742152960396f * (x2 - y2);
        const float Y9  = 0.5900435899266435f * y * (3.0f * x2 - y2);
        const float Y10 = 2.890611442640554f  * x * y * zc;
        const float Y11 = 0.4570457994644658f * y * (5.0f * z2 - 1.0f);
        const float Y12 = 0.3731763325901154f * zc * (5.0f * z2 - 3.0f);
        const float Y13 = 0.4570457994644658f * x * (5.0f * z2 - 1.0f);
        const float Y14 = 1.445305721320277f  * zc * (x2 - y2);
        const float Y15 = 0.5900435899266435f * x * (x2 - 3.0f * y2);

        float s0, s1, s2, s3;
        if (mq == 0)      { s0 = Y0;  s1 = Y1;  s2 = Y2;  s3 = Y3;  }
        else if (mq == 1) { s0 = Y4;  s1 = Y5;  s2 = Y6;  s3 = Y7;  }
        else if (mq == 2) { s0 = Y8;  s1 = Y9;  s2 = Y10; s3 = Y11; }
        else              { s0 = Y12; s1 = Y13; s2 = Y14; s3 = Y15; }

        // out offset: rb + quad*4 ; quads pos and pos+16.
        const size_t base = (size_t)rb + (size_t)pos * 4;
        if (valid) {
            red_add_v4(out + base,      aA0 * s0, aB0 * s1, aB0 * s2, aB0 * s3);
            red_add_v4(out + base + 64, aA1 * s0, aB1 * s1, aB1 * s2, aB1 * s3);
        }
    }
}

extern "C" void kernel_launch(void* const* d_in, const int* in_sizes, int n_in,
                              void* d_out, int out_size) {
    const float* dist = (const float*)d_in[0];
    const float* dirs = (const float*)d_in[1];
    const float* W    = (const float*)d_in[2];
    // d_in[3] = centers: analytic linspace(0, RC, 16)
    const int* z      = (const int*)d_in[4];
    const int* idx_i  = (const int*)d_in[5];
    const int* idx_j  = (const int*)d_in[6];
    int n_edges = in_sizes[0];
    if (n_edges > MAX_EDGES) n_edges = MAX_EDGES;   // scratch capacity (spec: 800000)

    cudaMemsetAsync(d_out, 0, (size_t)out_size * sizeof(float), 0);

    build_table_kernel<<<((NKNOT + 1) * 16 + 255) / 256, 256>>>(W);
    build_rid_kernel<<<(n_edges + 511) / 512, 512>>>(idx_i, idx_j, z, n_edges);

    const int block = 256;
    const int grid  = 2368;    // 148 SMs x 16 blocks, grid-stride over edge pairs
    sph_expand_kernel<<<grid, block>>>(dist, dirs, (float*)d_out, n_edges);
}

// round 10
// speedup vs baseline: 1.5309x; 1.0458x over previous
#include <cuda_runtime.h>

// SphericalExpansion: per-edge radial×angular outer product scattered into
// out[idx_i, z[idx_j], n, m]  (20000, 4, 8, 16) fp32.
//
// RIln(d) = fc(d) * sum_k exp(-2(d-c_k)^2) * W[l*8+n, k] is a smooth 1-D
// function of d per row -> precomputed on a 2048-interval grid, packed
// T[j][pos] = (RIln[ln0](d_j), RIln[ln1](d_j)); hot loop does a linear
// interp (packed f32x2), zero MUFU.
//
// Hot loop: 4 edges per warp-iter (two independent pairs for ILP). Within a
// pair, halves h own one edge; lane (h,pos) covers rows ln0=(pos>>2)*8+(pos&3),
// ln1=ln0+4, bridges via 4 uniform-register shuffles to scatter quads pos,
// pos+16, commits 2x red.global.add.v4.f32.

#define PI_F 3.14159265358979f
#define MAX_EDGES 800000
#define NKNOT 2048
#define DSCALE ((float)NKNOT / 5.0f)
#define DSTEP  (5.0f / (float)NKNOT)
#define TAB_N  ((NKNOT + 1) * 16)

__device__ int    g_rbase[MAX_EDGES];
__device__ float2 g_tab[TAB_N];   // [knot][pos] = (row ln0, row ln1)

typedef unsigned long long u64_t;

__device__ __forceinline__ u64_t pack2(float lo, float hi) {
    u64_t r; asm("mov.b64 %0, {%1, %2};" : "=l"(r) : "f"(lo), "f"(hi)); return r;
}
__device__ __forceinline__ void unpack2(u64_t v, float& lo, float& hi) {
    asm("mov.b64 {%0, %1}, %2;" : "=f"(lo), "=f"(hi) : "l"(v));
}
__device__ __forceinline__ u64_t fma2(u64_t a, u64_t b, u64_t c) {
    u64_t d; asm("fma.rn.f32x2 %0, %1, %2, %3;" : "=l"(d) : "l"(a), "l"(b), "l"(c));
    return d;
}
__device__ __forceinline__ u64_t mul2(u64_t a, u64_t b) {
    u64_t d; asm("mul.rn.f32x2 %0, %1, %2;" : "=l"(d) : "l"(a), "l"(b));
    return d;
}
__device__ __forceinline__ void red_add_v4(float* p, float a, float b, float c, float d) {
    asm volatile("red.global.add.v4.f32 [%0], {%1,%2,%3,%4};"
                 :: "l"(p), "f"(a), "f"(b), "f"(c), "f"(d) : "memory");
}

// ---- fused prep: radial table (threads < TAB_N) + rbase (grid-stride) ----
__global__ __launch_bounds__(512)
void prep_kernel(const float* __restrict__ W,
                 const int*   __restrict__ idx_i,
                 const int*   __restrict__ idx_j,
                 const int*   __restrict__ zarr,
                 int n_edges)
{
    const int t  = blockIdx.x * blockDim.x + threadIdx.x;
    const int nt = gridDim.x * blockDim.x;

    if (t < TAB_N) {
        int j   = t >> 4;
        int pos = t & 15;
        int ln0 = (pos >> 2) * 8 + (pos & 3);
        int ln1 = ln0 + 4;

        float d  = (float)j * DSTEP;
        float tt = fminf(fmaxf((d - 4.5f) * 2.0f, 0.0f), 1.0f);
        float fc = 0.5f * (cosf(tt * PI_F) + 1.0f);

        float a0 = 0.f, a1 = 0.f;
        #pragma unroll
        for (int k = 0; k < 16; ++k) {
            float ck = (float)k * (5.0f / 15.0f);
            float u  = d - ck;
            float g  = expf(-2.0f * u * u);
            a0 = fmaf(g, W[ln0 * 16 + k], a0);
            a1 = fmaf(g, W[ln1 * 16 + k], a1);
        }
        g_tab[t] = make_float2(a0 * fc, a1 * fc);
    }

    for (int e = t; e < n_edges; e += nt)
        g_rbase[e] = (idx_i[e] * 4 + zarr[idx_j[e]]) * 128;
}

__global__ __launch_bounds__(256, 4)
void sph_expand_kernel(
    const float* __restrict__ dist,
    const float* __restrict__ dirs,
    float*       __restrict__ out,    // (N_ATOMS, 4, 8, 16)
    int n_edges)
{
    const unsigned FULL = 0xffffffffu;
    const int lane = threadIdx.x & 31;
    const int h    = lane >> 4;        // which edge of a pair
    const int pos  = lane & 15;

    const int gw = (blockIdx.x * blockDim.x + threadIdx.x) >> 5;
    const int nw = (gridDim.x * blockDim.x) >> 5;

    // scatter role: quads pos and pos+16. Quad q: n0=q>>2, mq=q&3.
    const int n0 = pos >> 2;
    const int mq = pos & 3;
    const int lA = (mq == 0) ? 0 : (mq == 3 ? 3 : 2);
    const int lB = (mq == 0) ? 1 : (mq == 1 ? 2 : 3);
    const int srcA = (lane & 16) + lA * 4 + n0;
    const int srcB = (lane & 16) + lB * 4 + n0;

    for (int e0 = 4 * gw; e0 < n_edges; e0 += 4 * nw) {
        // ---------- batched loads for both pairs ----------
        const int  eA = e0 + h;                 // pair A
        const int  eB = e0 + 2 + h;             // pair B
        const bool vA = eA < n_edges;
        const bool vB = eB < n_edges;
        const int  la = vA ? eA : (n_edges - 1);
        const int  lb = vB ? eB : (n_edges - 1);

        const int   rbA = g_rbase[la];
        const float dA  = dist[la];
        const float xA  = dirs[3 * la + 0];
        const float yA  = dirs[3 * la + 1];
        const float zA  = dirs[3 * la + 2];

        const int   rbB = g_rbase[lb];
        const float dB  = dist[lb];
        const float xB  = dirs[3 * lb + 0];
        const float yB  = dirs[3 * lb + 1];
        const float zB  = dirs[3 * lb + 2];

        // ---------- radial lerp, pair A ----------
        float uA = dA * DSCALE;
        int   jA = __float2int_rd(uA);
        jA = min(max(jA, 0), NKNOT - 1);
        float fA = uA - (float)jA;
        const float2 a0v = g_tab[jA * 16 + pos];
        const float2 a1v = g_tab[(jA + 1) * 16 + pos];

        // ---------- radial lerp, pair B ----------
        float uB = dB * DSCALE;
        int   jB = __float2int_rd(uB);
        jB = min(max(jB, 0), NKNOT - 1);
        float fB = uB - (float)jB;
        const float2 b0v = g_tab[jB * 16 + pos];
        const float2 b1v = g_tab[(jB + 1) * 16 + pos];

        u64_t accA = fma2(pack2(a1v.x, a1v.y), pack2(fA, fA),
                          mul2(pack2(a0v.x, a0v.y), pack2(1.0f - fA, 1.0f - fA)));
        u64_t accB = fma2(pack2(b1v.x, b1v.y), pack2(fB, fB),
                          mul2(pack2(b0v.x, b0v.y), pack2(1.0f - fB, 1.0f - fB)));

        float cA0, cA1, cB0, cB1;
        unpack2(accA, cA0, cA1);
        unpack2(accB, cB0, cB1);

        // ---------- bridges: 8 shuffles total ----------
        const float aA0 = __shfl_sync(FULL, cA0, srcA);
        const float aB0 = __shfl_sync(FULL, cA0, srcB);
        const float aA1 = __shfl_sync(FULL, cA1, srcA);
        const float aB1 = __shfl_sync(FULL, cA1, srcB);
        const float bA0 = __shfl_sync(FULL, cB0, srcA);
        const float bB0 = __shfl_sync(FULL, cB0, srcB);
        const float bA1 = __shfl_sync(FULL, cB1, srcA);
        const float bB1 = __shfl_sync(FULL, cB1, srcB);

        // ---------- Ylm + scatter, pair A ----------
        {
            const float x = xA, y = yA, zc = zA;
            const float x2 = x * x, y2 = y * y, z2 = zc * zc;
            const float Y0  = 0.28209479177387814f;
            const float Y1  = 0.4886025119029199f * y;
            const float Y2  = 0.4886025119029199f * zc;
            const float Y3  = 0.4886025119029199f * x;
            const float Y4  = 1.0925484305920792f * x * y;
            const float Y5  = 1.0925484305920792f * y * zc;
            const float Y6  = 0.31539156525252005f * (3.0f * z2 - 1.0f);
            const float Y7  = 1.0925484305920792f * x * zc;
            const float Y8  = 0.5462742152960396f * (x2 - y2);
            const float Y9  = 0.5900435899266435f * y * (3.0f * x2 - y2);
            const float Y10 = 2.890611442640554f  * x * y * zc;
            const float Y11 = 0.4570457994644658f * y * (5.0f * z2 - 1.0f);
            const float Y12 = 0.3731763325901154f * zc * (5.0f * z2 - 3.0f);
            const float Y13 = 0.4570457994644658f * x * (5.0f * z2 - 1.0f);
            const float Y14 = 1.445305721320277f  * zc * (x2 - y2);
            const float Y15 = 0.5900435899266435f * x * (x2 - 3.0f * y2);

            float s0, s1, s2, s3;
            if (mq == 0)      { s0 = Y0;  s1 = Y1;  s2 = Y2;  s3 = Y3;  }
            else if (mq == 1) { s0 = Y4;  s1 = Y5;  s2 = Y6;  s3 = Y7;  }
            else if (mq == 2) { s0 = Y8;  s1 = Y9;  s2 = Y10; s3 = Y11; }
            else              { s0 = Y12; s1 = Y13; s2 = Y14; s3 = Y15; }

            const size_t base = (size_t)rbA + (size_t)pos * 4;
            if (vA) {
                red_add_v4(out + base,      aA0 * s0, aB0 * s1, aB0 * s2, aB0 * s3);
                red_add_v4(out + base + 64, aA1 * s0, aB1 * s1, aB1 * s2, aB1 * s3);
            }
        }

        // ---------- Ylm + scatter, pair B ----------
        {
            const float x = xB, y = yB, zc = zB;
            const float x2 = x * x, y2 = y * y, z2 = zc * zc;
            const float Y0  = 0.28209479177387814f;
            const float Y1  = 0.4886025119029199f * y;
            const float Y2  = 0.4886025119029199f * zc;
            const float Y3  = 0.4886025119029199f * x;
            const float Y4  = 1.0925484305920792f * x * y;
            const float Y5  = 1.0925484305920792f * y * zc;
            const float Y6  = 0.31539156525252005f * (3.0f * z2 - 1.0f);
            const float Y7  = 1.0925484305920792f * x * zc;
            const float Y8  = 0.5462742152960396f * (x2 - y2);
            const float Y9  = 0.5900435899266435f * y * (3.0f * x2 - y2);
            const float Y10 = 2.890611442640554f  * x * y * zc;
            const float Y11 = 0.4570457994644658f * y * (5.0f * z2 - 1.0f);
            const float Y12 = 0.3731763325901154f * zc * (5.0f * z2 - 3.0f);
            const float Y13 = 0.4570457994644658f * x * (5.0f * z2 - 1.0f);
            const float Y14 = 1.445305721320277f  * zc * (x2 - y2);
            const float Y15 = 0.5900435899266435f * x * (x2 - 3.0f * y2);

            float s0, s1, s2, s3;
            if (mq == 0)      { s0 = Y0;  s1 = Y1;  s2 = Y2;  s3 = Y3;  }
            else if (mq == 1) { s0 = Y4;  s1 = Y5;  s2 = Y6;  s3 = Y7;  }
            else if (mq == 2) { s0 = Y8;  s1 = Y9;  s2 = Y10; s3 = Y11; }
            else              { s0 = Y12; s1 = Y13; s2 = Y14; s3 = Y15; }

            const size_t base = (size_t)rbB + (size_t)pos * 4;
            if (vB) {
                red_add_v4(out + base,      bA0 * s0, bB0 * s1, bB0 * s2, bB0 * s3);
                red_add_v4(out + base + 64, bA1 * s0, bB1 * s1, bB1 * s2, bB1 * s3);
            }
        }
    }
}

extern "C" void kernel_launch(void* const* d_in, const int* in_sizes, int n_in,
                              void* d_out, int out_size) {
    const float* dist = (const float*)d_in[0];
    const float* dirs = (const float*)d_in[1];
    const float* W    = (const float*)d_in[2];
    // d_in[3] = centers: analytic linspace(0, RC, 16)
    const int* z      = (const int*)d_in[4];
    const int* idx_i  = (const int*)d_in[5];
    const int* idx_j  = (const int*)d_in[6];
    int n_edges = in_sizes[0];
    if (n_edges > MAX_EDGES) n_edges = MAX_EDGES;   // scratch capacity (spec: 800000)

    cudaMemsetAsync(d_out, 0, (size_t)out_size * sizeof(float), 0);

    prep_kernel<<<(n_edges + 511) / 512, 512>>>(W, idx_i, idx_j, z, n_edges);

    const int block = 256;
    const int grid  = 2368;    // 148 SMs x 16 blocks, grid-stride over 4-edge groups
    sph_expand_kernel<<<grid, block>>>(dist, dirs, (float*)d_out, n_edges);
}